// round 7
// baseline (speedup 1.0000x reference)
#include <cuda_runtime.h>
#include <cstdint>

// out[b,i,j] = 1.0f iff |i-j| <= 10 and mask[b, min(i,j)+1 .. max(i,j)] all zero.
// Row i is a contiguous run of ones [max(0,i-dl), min(L-1,i+dr)].
// One warp per row; ballot over the 21-element mask window gives (dl,dr);
// 8 coalesced streaming STG.128 per lane fill the 4KB row.
// Persistent grid (SMs*8 blocks) removes wave-tail imbalance.

static constexpr int B = 32;
static constexpr int L = 1024;
static constexpr int ROWS = B * L;   // 32768

__global__ __launch_bounds__(256)
void band_mask_persistent(const int* __restrict__ mask,
                          float4* __restrict__ out,
                          int warp_stride) {
    const int lane = threadIdx.x & 31;
    int warp = (blockIdx.x * blockDim.x + threadIdx.x) >> 5;

    for (; warp < ROWS; warp += warp_stride) {
        const int b = warp >> 10;          // L = 1024
        const int i = warp & (L - 1);
        const int* __restrict__ mrow = mask + (b << 10);

        // Lane t in [0,20] observes pos = i-10+t; open = in-range && mask==0.
        int open = 0;
        const int pos = i - 10 + lane;
        if (lane <= 20 && pos >= 0 && pos < L)
            open = (mrow[pos] == 0);
        const unsigned blocked = ~__ballot_sync(0xffffffffu, open);

        // Left: dl = 10 - (highest blocked bit among bits 1..10); sentinel bit0.
        const unsigned zl = (blocked & 0x7FEu) | 1u;
        const int dl = 10 - (31 - __clz(zl));
        // Right: dr = consecutive open bits starting at bit 11 (cap 10).
        const unsigned zr = (blocked >> 11) & 0x3FFu;
        const int dr = __ffs(zr | 0x400u) - 1;

        int lo = i - dl; if (lo < 0) lo = 0;
        int hi = i + dr; if (hi > L - 1) hi = L - 1;   // safety clamp
        const unsigned span = (unsigned)(hi - lo);

        float4* __restrict__ orow = out + ((size_t)warp << 8);
#pragma unroll
        for (int k = 0; k < 8; k++) {
            const int q  = lane + (k << 5);
            const int j0 = q << 2;
            float4 v;
            v.x = ((unsigned)(j0     - lo) <= span) ? 1.0f : 0.0f;
            v.y = ((unsigned)(j0 + 1 - lo) <= span) ? 1.0f : 0.0f;
            v.z = ((unsigned)(j0 + 2 - lo) <= span) ? 1.0f : 0.0f;
            v.w = ((unsigned)(j0 + 3 - lo) <= span) ? 1.0f : 0.0f;
            __stcs(orow + q, v);   // streaming: write-once, evict-first
        }
    }
}

extern "C" void kernel_launch(void* const* d_in, const int* in_sizes, int n_in,
                              void* d_out, int out_size) {
    const int* mask = (const int*)d_in[0];
    float4* out = (float4*)d_out;

    int sms = 148;
    cudaDeviceGetAttribute(&sms, cudaDevAttrMultiProcessorCount, 0);

    const int block = 256;                 // 8 warps
    const int grid = sms * 8;              // full residency, persistent
    const int warp_stride = grid * (block / 32);

    band_mask_persistent<<<grid, block>>>(mask, out, warp_stride);
}

// round 8
// speedup vs baseline: 1.0476x; 1.0476x over previous
#include <cuda_runtime.h>
#include <cstdint>

// out[b,i,j] = 1.0f iff |i-j| <= 10 and mask[b, min(i,j)+1 .. max(i,j)] all zero.
// Row i is a contiguous run of ones [max(0,i-dl), min(L-1,i+dr)].
//
// R7 finding: STG-based variants pin at ~20.5us with L1TEX highest (~65%) and
// L2 at only 54% of the LTS cap -> SM global-store path is the limiter.
// This version builds each 4KB row in SMEM and drains it with a 1D TMA bulk
// store (cp.async.bulk shared::cta -> global), bypassing L1TEX entirely.

static constexpr int B = 32;
static constexpr int L = 1024;
static constexpr int ROWS = B * L;        // 32768
static constexpr int WARPS = 4;           // rows per block
static constexpr int ROW_BYTES = L * 4;   // 4096

__device__ __forceinline__ uint32_t smem_u32(const void* p) {
    uint32_t a;
    asm("{ .reg .u64 t; cvta.to.shared.u64 t, %1; cvt.u32.u64 %0, t; }"
        : "=r"(a) : "l"(p));
    return a;
}

__global__ __launch_bounds__(WARPS * 32)
void band_mask_tma(const int* __restrict__ mask, char* __restrict__ out) {
    __shared__ __align__(128) float srows[WARPS][L];   // 16 KB

    const int wid  = threadIdx.x >> 5;
    const int lane = threadIdx.x & 31;
    const int row  = blockIdx.x * WARPS + wid;          // 0 .. ROWS-1
    const int b = row >> 10;                            // L = 1024
    const int i = row & (L - 1);
    const int* __restrict__ mrow = mask + (b << 10);

    // Band bounds via ballot over the 21-element mask window.
    int open = 0;
    const int pos = i - 10 + lane;
    if (lane <= 20 && pos >= 0 && pos < L)
        open = (mrow[pos] == 0);
    const unsigned blocked = ~__ballot_sync(0xffffffffu, open);

    const unsigned zl = (blocked & 0x7FEu) | 1u;        // bits 1..10, sentinel bit0
    const int dl = 10 - (31 - __clz(zl));
    const unsigned zr = (blocked >> 11) & 0x3FFu;       // bits 11..20
    const int dr = __ffs(zr | 0x400u) - 1;

    int lo = i - dl; if (lo < 0) lo = 0;
    int hi = i + dr; if (hi > L - 1) hi = L - 1;
    const unsigned span = (unsigned)(hi - lo);

    // Build the row in SMEM: 8 x STS.128 per lane.
    float4* __restrict__ srow = reinterpret_cast<float4*>(srows[wid]);
#pragma unroll
    for (int k = 0; k < 8; k++) {
        const int q  = lane + (k << 5);
        const int j0 = q << 2;
        float4 v;
        v.x = ((unsigned)(j0     - lo) <= span) ? 1.0f : 0.0f;
        v.y = ((unsigned)(j0 + 1 - lo) <= span) ? 1.0f : 0.0f;
        v.z = ((unsigned)(j0 + 2 - lo) <= span) ? 1.0f : 0.0f;
        v.w = ((unsigned)(j0 + 3 - lo) <= span) ? 1.0f : 0.0f;
        srow[q] = v;
    }
    __syncwarp();

    // One lane drains the row to GMEM via 1D TMA bulk store (bypasses L1TEX).
    if (lane == 0) {
        asm volatile("fence.proxy.async.shared::cta;" ::: "memory");
        const uint32_t saddr = smem_u32(&srows[wid][0]);
        char* gaddr = out + (size_t)row * ROW_BYTES;
        asm volatile(
            "cp.async.bulk.global.shared::cta.bulk_group [%0], [%1], %2;"
            :: "l"(gaddr), "r"(saddr), "n"(ROW_BYTES) : "memory");
        asm volatile("cp.async.bulk.commit_group;" ::: "memory");
        // SMEM must stay valid until the bulk read completes.
        asm volatile("cp.async.bulk.wait_group.read 0;" ::: "memory");
    }
}

extern "C" void kernel_launch(void* const* d_in, const int* in_sizes, int n_in,
                              void* d_out, int out_size) {
    const int* mask = (const int*)d_in[0];
    char* out = (char*)d_out;

    const int grid = ROWS / WARPS;        // 8192 blocks, 4 rows each
    band_mask_tma<<<grid, WARPS * 32>>>(mask, out);
}

// round 10
// speedup vs baseline: 1.1014x; 1.0514x over previous
#include <cuda_runtime.h>
#include <cstdint>

// out[b,i,j] = 1.0f iff |i-j| <= 10 and mask[b, min(i,j)+1 .. max(i,j)] all zero.
// Row i is a contiguous run of ones [max(0,i-dl), min(L-1,i+dr)].
//
// R8 experiment: steady-state is L2->DRAM write-drain bound (134MB/24.2us =
// 5.5 TB/s sustained; isolated ncu run retires with ~60MB still dirty in L2).
// Use write-through stores (__stwt) so DRAM writes stream during execution
// instead of bursting at replay boundaries. Everything else unchanged from
// the best STG variant.

static constexpr int B = 32;
static constexpr int L = 1024;
static constexpr int ROWS = B * L;      // 32768 warps, one per output row

__global__ __launch_bounds__(256)
void band_mask_wt(const int* __restrict__ mask, float4* __restrict__ out) {
    const int warp = (blockIdx.x * blockDim.x + threadIdx.x) >> 5;
    const int lane = threadIdx.x & 31;
    const int b = warp >> 10;           // L = 1024
    const int i = warp & (L - 1);

    const int* __restrict__ mrow = mask + (b << 10);

    // Band bounds via ballot over the 21-element mask window.
    int open = 0;
    const int pos = i - 10 + lane;
    if (lane <= 20 && pos >= 0 && pos < L)
        open = (mrow[pos] == 0);
    const unsigned blocked = ~__ballot_sync(0xffffffffu, open);

    const unsigned zl = (blocked & 0x7FEu) | 1u;     // bits 1..10, sentinel bit0
    const int dl = 10 - (31 - __clz(zl));
    const unsigned zr = (blocked >> 11) & 0x3FFu;    // bits 11..20
    const int dr = __ffs(zr | 0x400u) - 1;

    int lo = i - dl; if (lo < 0) lo = 0;
    int hi = i + dr; if (hi > L - 1) hi = L - 1;
    const unsigned span = (unsigned)(hi - lo);

    // Fill the 1024-float row: 8 x write-through STG.128 per lane, coalesced.
    float4* __restrict__ orow = out + ((size_t)warp << 8);
#pragma unroll
    for (int k = 0; k < 8; k++) {
        const int q  = lane + (k << 5);
        const int j0 = q << 2;
        float4 v;
        v.x = ((unsigned)(j0     - lo) <= span) ? 1.0f : 0.0f;
        v.y = ((unsigned)(j0 + 1 - lo) <= span) ? 1.0f : 0.0f;
        v.z = ((unsigned)(j0 + 2 - lo) <= span) ? 1.0f : 0.0f;
        v.w = ((unsigned)(j0 + 3 - lo) <= span) ? 1.0f : 0.0f;
        __stwt(orow + q, v);            // write-through: stream to DRAM now
    }
}

extern "C" void kernel_launch(void* const* d_in, const int* in_sizes, int n_in,
                              void* d_out, int out_size) {
    const int* mask = (const int*)d_in[0];
    float4* out = (float4*)d_out;

    const int block = 256;
    const int grid = ROWS / (block / 32);   // 4096 blocks of 8 warps

    band_mask_wt<<<grid, block>>>(mask, out);
}